// round 16
// baseline (speedup 1.0000x reference)
#include <cuda_runtime.h>
#include <cuda_fp16.h>
#include <math.h>
#include <stdint.h>

#define BB 2
#define SS 2048
#define DD 768
#define HH 12
#define DH 64
#define MM (BB*SS)
#define DP (DD/2)     // 384 u32 pairs per row
#define LOG2E 1.4426950408889634f

// scratch (no allocations allowed — __device__ globals are the sanctioned path)
__device__ float g_v[MM*DD];
__device__ float g_ctx[MM*DD];
// packed fp16 hi/lo splits (Q pre-scaled by log2e)
__device__ uint32_t g_qh[MM*DP];
__device__ uint32_t g_ql[MM*DP];
__device__ uint32_t g_kh[MM*DP];
__device__ uint32_t g_kl[MM*DP];
__device__ uint32_t g_vth[MM*DP];   // V transposed: [(b*HH+h)*64 + d][kp(1024)]
__device__ uint32_t g_vtl[MM*DP];

__device__ __forceinline__ void mma_f16(float* d,
                                        const uint32_t* a,
                                        const uint32_t* b) {
    asm volatile(
        "mma.sync.aligned.m16n8k16.row.col.f32.f16.f16.f32 "
        "{%0,%1,%2,%3}, {%4,%5,%6,%7}, {%8,%9}, {%0,%1,%2,%3};"
        : "+f"(d[0]), "+f"(d[1]), "+f"(d[2]), "+f"(d[3])
        : "r"(a[0]), "r"(a[1]), "r"(a[2]), "r"(a[3]),
          "r"(b[0]), "r"(b[1]));
}

__device__ __forceinline__ void ldm4(uint32_t addr, uint32_t* r) {
    asm volatile("ldmatrix.sync.aligned.m8n8.x4.shared.b16 {%0,%1,%2,%3}, [%4];"
        : "=r"(r[0]), "=r"(r[1]), "=r"(r[2]), "=r"(r[3]) : "r"(addr));
}

__device__ __forceinline__ float ex2(float x) {
    float y;
    asm("ex2.approx.f32 %0, %1;" : "=f"(y) : "f"(x));
    return y;
}

// pack two floats into one fp16x2 (a -> low half, b -> high half)
__device__ __forceinline__ uint32_t pack2h(float a, float b) {
    uint32_t r;
    asm("cvt.rn.f16x2.f32 %0, %1, %2;" : "=r"(r) : "f"(b), "f"(a));
    return r;
}

// split (a,b) into packed fp16 hi-pair and lo-pair (low half = first element)
__device__ __forceinline__ void split2h(float a, float b,
                                        uint32_t& hi, uint32_t& lo) {
    __half ah = __float2half_rn(a);
    __half bh = __float2half_rn(b);
    hi = (uint32_t)__half_as_ushort(ah) |
         ((uint32_t)__half_as_ushort(bh) << 16);
    lo = pack2h(a - __half2float(ah), b - __half2float(bh));
}

__device__ __forceinline__ void cp16(uint32_t saddr, const void* gaddr) {
    asm volatile("cp.async.ca.shared.global [%0], [%1], 16;"
                 :: "r"(saddr), "l"(gaddr));
}
#define CP_COMMIT() asm volatile("cp.async.commit_group;" ::: "memory")
#define CP_WAIT1()  asm volatile("cp.async.wait_group 1;" ::: "memory")
#define CP_WAIT0()  asm volatile("cp.async.wait_group 0;" ::: "memory")

// ---------------------------------------------------------------------------
// fp16x2 (3-term) mma.sync GEMM with selectable epilogue.
// grid.z selects weight/bias/output set (fused QKV in one launch).
// ---------------------------------------------------------------------------
struct GemmArgs {
    const float* W[3];
    const float* bias[3];
    float*    Cf[3];
    uint32_t* Ch[3];
    uint32_t* Cl[3];
    float     scale[3];
};

#define AST 9      // A smem u32 stride
#define BST 136    // B smem u32 stride

__global__ void __launch_bounds__(256)
gemm_f16_kernel(const float* __restrict__ A, GemmArgs args)
{
    __shared__ uint32_t AsH[128 * AST];
    __shared__ uint32_t AsL[128 * AST];
    __shared__ uint32_t BsH[8 * BST];
    __shared__ uint32_t BsL[8 * BST];
    __shared__ float sbias[128];

    const int z = blockIdx.z;
    const float* __restrict__ W    = args.W[z];
    const float* __restrict__ bias = args.bias[z];
    float*    Cf = args.Cf[z];
    uint32_t* Ch = args.Ch[z];
    uint32_t* Cl = args.Cl[z];
    const float scl = args.scale[z];

    const int tid  = threadIdx.x;
    const int warp = tid >> 5;
    const int lane = tid & 31;
    const int g    = lane >> 2;
    const int tg   = lane & 3;
    const int wm   = warp >> 2;
    const int wn   = warp & 3;
    const int m0   = blockIdx.y * 128;
    const int n0   = blockIdx.x * 128;

    if (tid < 128) sbias[tid] = bias[n0 + tid];

    const int ar0 = tid >> 2;
    const int aq0 = tid & 3;
    const int ar1 = (tid + 256) >> 2;
    const int aq1 = (tid + 256) & 3;
    const int bkp = tid >> 5;
    const int bnq = (tid & 31) << 2;

    float acc[4][4][4];
#pragma unroll
    for (int i = 0; i < 4; i++)
#pragma unroll
        for (int j = 0; j < 4; j++)
#pragma unroll
            for (int q = 0; q < 4; q++) acc[i][j][q] = 0.0f;

    float4 ra0, ra1, rb0, rb1;

    ra0 = *reinterpret_cast<const float4*>(&A[(long)(m0 + ar0) * DD + aq0 * 4]);
    ra1 = *reinterpret_cast<const float4*>(&A[(long)(m0 + ar1) * DD + aq1 * 4]);
    rb0 = *reinterpret_cast<const float4*>(&W[(long)(2 * bkp) * DD + n0 + bnq]);
    rb1 = *reinterpret_cast<const float4*>(&W[(long)(2 * bkp + 1) * DD + n0 + bnq]);

#define STORE_TILES() do {                                                   \
    split2h(ra0.x, ra0.y, AsH[ar0 * AST + aq0 * 2],     AsL[ar0 * AST + aq0 * 2]); \
    split2h(ra0.z, ra0.w, AsH[ar0 * AST + aq0 * 2 + 1], AsL[ar0 * AST + aq0 * 2 + 1]); \
    split2h(ra1.x, ra1.y, AsH[ar1 * AST + aq1 * 2],     AsL[ar1 * AST + aq1 * 2]); \
    split2h(ra1.z, ra1.w, AsH[ar1 * AST + aq1 * 2 + 1], AsL[ar1 * AST + aq1 * 2 + 1]); \
    split2h(rb0.x, rb1.x, BsH[bkp * BST + bnq],     BsL[bkp * BST + bnq]);     \
    split2h(rb0.y, rb1.y, BsH[bkp * BST + bnq + 1], BsL[bkp * BST + bnq + 1]); \
    split2h(rb0.z, rb1.z, BsH[bkp * BST + bnq + 2], BsL[bkp * BST + bnq + 2]); \
    split2h(rb0.w, rb1.w, BsH[bkp * BST + bnq + 3], BsL[bkp * BST + bnq + 3]); \
} while (0)

    STORE_TILES();
    __syncthreads();

    const int NITER = DD / 16;   // 48
    for (int it = 0; it < NITER; it++) {
        if (it + 1 < NITER) {
            const int k0 = (it + 1) * 16;
            ra0 = *reinterpret_cast<const float4*>(&A[(long)(m0 + ar0) * DD + k0 + aq0 * 4]);
            ra1 = *reinterpret_cast<const float4*>(&A[(long)(m0 + ar1) * DD + k0 + aq1 * 4]);
            rb0 = *reinterpret_cast<const float4*>(&W[(long)(k0 + 2 * bkp) * DD + n0 + bnq]);
            rb1 = *reinterpret_cast<const float4*>(&W[(long)(k0 + 2 * bkp + 1) * DD + n0 + bnq]);
        }

        uint32_t afH[4][4], afL[4][4], bfH[4][2], bfL[4][2];
#pragma unroll
        for (int mi = 0; mi < 4; mi++) {
            const int r = wm * 64 + mi * 16 + g;
            afH[mi][0] = AsH[r * AST + tg];
            afH[mi][1] = AsH[(r + 8) * AST + tg];
            afH[mi][2] = AsH[r * AST + tg + 4];
            afH[mi][3] = AsH[(r + 8) * AST + tg + 4];
            afL[mi][0] = AsL[r * AST + tg];
            afL[mi][1] = AsL[(r + 8) * AST + tg];
            afL[mi][2] = AsL[r * AST + tg + 4];
            afL[mi][3] = AsL[(r + 8) * AST + tg + 4];
        }
#pragma unroll
        for (int ni = 0; ni < 4; ni++) {
            const int c = wn * 32 + ni * 8 + g;
            bfH[ni][0] = BsH[tg * BST + c];
            bfH[ni][1] = BsH[(tg + 4) * BST + c];
            bfL[ni][0] = BsL[tg * BST + c];
            bfL[ni][1] = BsL[(tg + 4) * BST + c];
        }
#pragma unroll
        for (int mi = 0; mi < 4; mi++)
#pragma unroll
            for (int ni = 0; ni < 4; ni++) {
                mma_f16(acc[mi][ni], afH[mi], bfL[ni]);
                mma_f16(acc[mi][ni], afL[mi], bfH[ni]);
                mma_f16(acc[mi][ni], afH[mi], bfH[ni]);
            }
        __syncthreads();
        if (it + 1 < NITER) {
            STORE_TILES();
            __syncthreads();
        }
    }

    // epilogue
    const int rr = lane >> 2;
    const int cc = (lane & 3) * 2;
    if (Ch) {
        // packed fp16 hi/lo output, optionally scaled (Q: log2e) (Q/K path)
#pragma unroll
        for (int mi = 0; mi < 4; mi++) {
#pragma unroll
            for (int ni = 0; ni < 4; ni++) {
                const int col = wn * 32 + ni * 8 + cc;
                const int row = m0 + wm * 64 + mi * 16 + rr;
                const int pc  = (n0 + col) >> 1;
                const float v0 = (acc[mi][ni][0] + sbias[col]) * scl;
                const float v1 = (acc[mi][ni][1] + sbias[col + 1]) * scl;
                const float v2 = (acc[mi][ni][2] + sbias[col]) * scl;
                const float v3 = (acc[mi][ni][3] + sbias[col + 1]) * scl;
                uint32_t hi, lo;
                split2h(v0, v1, hi, lo);
                Ch[(long)row * DP + pc] = hi;
                Cl[(long)row * DP + pc] = lo;
                split2h(v2, v3, hi, lo);
                Ch[(long)(row + 8) * DP + pc] = hi;
                Cl[(long)(row + 8) * DP + pc] = lo;
            }
        }
    } else {
        // float output (V and O paths)
#pragma unroll
        for (int mi = 0; mi < 4; mi++) {
#pragma unroll
            for (int ni = 0; ni < 4; ni++) {
                const int col = wn * 32 + ni * 8 + cc;
                const int row = m0 + wm * 64 + mi * 16 + rr;
                float2 o0, o1;
                o0.x = acc[mi][ni][0] + sbias[col];
                o0.y = acc[mi][ni][1] + sbias[col + 1];
                o1.x = acc[mi][ni][2] + sbias[col];
                o1.y = acc[mi][ni][3] + sbias[col + 1];
                *reinterpret_cast<float2*>(&Cf[(long)row * DD + n0 + col]) = o0;
                *reinterpret_cast<float2*>(&Cf[(long)(row + 8) * DD + n0 + col]) = o1;
            }
        }
    }
}

// ---------------------------------------------------------------------------
// Pre-pass: V transpose + fp16 split, tiled through smem.
// Output layout: g_vth[(bh*64 + d) * 1024 + kp]
// grid (32 kp-blocks, 24 bh), 256 threads.
// ---------------------------------------------------------------------------
__global__ void __launch_bounds__(256)
split_vt_kernel()
{
    __shared__ uint32_t sH[32 * 65];
    __shared__ uint32_t sL[32 * 65];

    const int tid = threadIdx.x;
    const int kp0 = blockIdx.x * 32;
    const int bh  = blockIdx.y;
    const int b   = bh / HH;
    const int h   = bh % HH;

    // load + split: 32 kp x 64 d
#pragma unroll
    for (int p = 0; p < 8; p++) {
        const int idx = tid + p * 256;
        const int kp = idx >> 6, d = idx & 63;
        const long base = (long)(b * SS + 2 * (kp0 + kp)) * DD + h * DH + d;
        uint32_t hi, lo;
        split2h(g_v[base], g_v[base + DD], hi, lo);
        sH[kp * 65 + d] = hi;
        sL[kp * 65 + d] = lo;
    }
    __syncthreads();

    // write transposed: rows = d, coalesced along kp
#pragma unroll
    for (int p = 0; p < 8; p++) {
        const int idx = tid + p * 256;
        const int d = idx >> 5, kp = idx & 31;
        const long o = ((long)bh * 64 + d) * 1024 + kp0 + kp;
        g_vth[o] = sH[kp * 65 + d];
        g_vtl[o] = sL[kp * 65 + d];
    }
}

// ---------------------------------------------------------------------------
// Flash attention: fp16 mma.sync + ldmatrix fragments, base-2 softmax,
// cp.async double-buffer. CTA = 128 queries x one (b,h); 8 warps (m16 each).
// K tiles: [key(64)][kp(32)] stride 36; V tiles: [d(64)][kp(32)] stride 36.
// ---------------------------------------------------------------------------
#define KTILE 2304                      // 64*36 u32 per array per stage
#define ATT_SMEM (8 * KTILE * 4)        // 73728 B
#define NT (SS/64)                      // 32

__global__ void __launch_bounds__(256)
attn_kernel()
{
    extern __shared__ uint32_t smatt[];
    uint32_t* sKh = smatt;
    uint32_t* sKl = smatt + 2 * KTILE;
    uint32_t* sVh = smatt + 4 * KTILE;
    uint32_t* sVl = smatt + 6 * KTILE;

    const uint32_t aKh = (uint32_t)__cvta_generic_to_shared(sKh);
    const uint32_t aKl = (uint32_t)__cvta_generic_to_shared(sKl);
    const uint32_t aVh = (uint32_t)__cvta_generic_to_shared(sVh);
    const uint32_t aVl = (uint32_t)__cvta_generic_to_shared(sVl);

    const int tid  = threadIdx.x;
    const int warp = tid >> 5;
    const int lane = tid & 31;
    const int g    = lane >> 2;
    const int tg   = lane & 3;
    const int wm   = warp * 16;
    const int bh   = blockIdx.y;
    const int b    = bh / HH;
    const int h    = bh % HH;
    const int q0   = blockIdx.x * 128;

    const uint32_t* khg = &g_kh[(long)(b * SS) * DP + h * 32];
    const uint32_t* klg = &g_kl[(long)(b * SS) * DP + h * 32];
    const uint32_t* vhg = &g_vth[(long)bh * 64 * 1024];
    const uint32_t* vlg = &g_vtl[(long)bh * 64 * 1024];

    // staging coords: rows (tid>>3, +32), chunk (tid&7)
    const int sr = tid >> 3;
    const int sc = (tid & 7) * 4;

#define ISSUE_STAGE(kt, st) do {                                             \
    const int _k0 = (kt) * 64;                                               \
    const uint32_t _so = (uint32_t)(st) * KTILE * 4;                         \
    cp16(aKh + _so + (sr * 36 + sc) * 4,        khg + (long)(_k0 + sr) * DP + sc); \
    cp16(aKh + _so + ((sr + 32) * 36 + sc) * 4, khg + (long)(_k0 + sr + 32) * DP + sc); \
    cp16(aKl + _so + (sr * 36 + sc) * 4,        klg + (long)(_k0 + sr) * DP + sc); \
    cp16(aKl + _so + ((sr + 32) * 36 + sc) * 4, klg + (long)(_k0 + sr + 32) * DP + sc); \
    cp16(aVh + _so + (sr * 36 + sc) * 4,        vhg + (long)sr * 1024 + (kt) * 32 + sc); \
    cp16(aVh + _so + ((sr + 32) * 36 + sc) * 4, vhg + (long)(sr + 32) * 1024 + (kt) * 32 + sc); \
    cp16(aVl + _so + (sr * 36 + sc) * 4,        vlg + (long)sr * 1024 + (kt) * 32 + sc); \
    cp16(aVl + _so + ((sr + 32) * 36 + sc) * 4, vlg + (long)(sr + 32) * 1024 + (kt) * 32 + sc); \
    CP_COMMIT();                                                             \
} while (0)

    // Q fragments to registers (once); g_qh pre-scaled by log2e
    uint32_t qH[4][4], qL[4][4];
    {
        const uint32_t* qh = &g_qh[(long)(b * SS + q0 + wm) * DP + h * 32];
        const uint32_t* ql = &g_ql[(long)(b * SS + q0 + wm) * DP + h * 32];
#pragma unroll
        for (int ks = 0; ks < 4; ks++) {
            const int c = ks * 8 + tg;
            qH[ks][0] = qh[g * DP + c];
            qH[ks][1] = qh[(g + 8) * DP + c];
            qH[ks][2] = qh[g * DP + c + 4];
            qH[ks][3] = qh[(g + 8) * DP + c + 4];
            qL[ks][0] = ql[g * DP + c];
            qL[ks][1] = ql[(g + 8) * DP + c];
            qL[ks][2] = ql[g * DP + c + 4];
            qL[ks][3] = ql[(g + 8) * DP + c + 4];
        }
    }

    // per-lane ldmatrix row offset (bytes): row = lane&7, matrix = lane>>3
    const uint32_t lmoff = (uint32_t)(((lane & 7) * 36 + (lane >> 3) * 4) * 4);

    float m0 = -INFINITY, m1 = -INFINITY, l0 = 0.0f, l1 = 0.0f;
    float o[8][4];
#pragma unroll
    for (int nt = 0; nt < 8; nt++)
#pragma unroll
        for (int q = 0; q < 4; q++) o[nt][q] = 0.0f;

    ISSUE_STAGE(0, 0);

    for (int kt = 0; kt < NT; kt++) {
        const int st = kt & 1;
        if (kt + 1 < NT) {
            ISSUE_STAGE(kt + 1, st ^ 1);
            CP_WAIT1();
        } else {
            CP_WAIT0();
        }
        __syncthreads();

        const uint32_t so = (uint32_t)st * KTILE * 4;
        const uint32_t kh_b = aKh + so + lmoff;
        const uint32_t kl_b = aKl + so + lmoff;
        const uint32_t vh_b = aVh + so + lmoff;
        const uint32_t vl_b = aVl + so + lmoff;

        // S = Q @ K^T (fp16x2, 3 terms), K fragments via ldmatrix.x4
        float s[8][4];
#pragma unroll
        for (int nt = 0; nt < 8; nt++)
#pragma unroll
            for (int q = 0; q < 4; q++) s[nt][q] = 0.0f;
#pragma unroll
        for (int nt = 0; nt < 8; nt++) {
            const uint32_t ro = (uint32_t)(nt * 1152);   // nt*8*36*4
#pragma unroll
            for (int j = 0; j < 2; j++) {
                uint32_t bh4[4], bl4[4];
                ldm4(kh_b + ro + j * 64, bh4);
                ldm4(kl_b + ro + j * 64, bl4);
                mma_f16(s[nt], qH[2 * j],     &bl4[0]);
                mma_f16(s[nt], qL[2 * j],     &bh4[0]);
                mma_f16(s[nt], qH[2 * j],     &bh4[0]);
                mma_f16(s[nt], qH[2 * j + 1], &bl4[2]);
                mma_f16(s[nt], qL[2 * j + 1], &bh4[2]);
                mma_f16(s[nt], qH[2 * j + 1], &bh4[2]);
            }
        }

        // base-2 register softmax: rows g (s[][0..1]) and g+8 (s[][2..3])
        {
            float mx0 = -INFINITY, mx1 = -INFINITY;
#pragma unroll
            for (int nt = 0; nt < 8; nt++) {
                mx0 = fmaxf(mx0, fmaxf(s[nt][0], s[nt][1]));
                mx1 = fmaxf(mx1, fmaxf(s[nt][2], s[nt][3]));
            }
            mx0 = fmaxf(mx0, __shfl_xor_sync(0xffffffffu, mx0, 1));
            mx0 = fmaxf(mx0, __shfl_xor_sync(0xffffffffu, mx0, 2));
            mx1 = fmaxf(mx1, __shfl_xor_sync(0xffffffffu, mx1, 1));
            mx1 = fmaxf(mx1, __shfl_xor_sync(0xffffffffu, mx1, 2));
            const float m0n = fmaxf(m0, mx0);
            const float m1n = fmaxf(m1, mx1);
            const float fr0 = ex2(m0 - m0n);
            const float fr1 = ex2(m1 - m1n);
            m0 = m0n; m1 = m1n;
            float sum0 = 0.0f, sum1 = 0.0f;
#pragma unroll
            for (int nt = 0; nt < 8; nt++) {
                s[nt][0] = ex2(s[nt][0] - m0n);
                s[nt][1] = ex2(s[nt][1] - m0n);
                s[nt][2] = ex2(s[nt][2] - m1n);
                s[nt][3] = ex2(s[nt][3] - m1n);
                sum0 += s[nt][0] + s[nt][1];
                sum1 += s[nt][2] + s[nt][3];
            }
            sum0 += __shfl_xor_sync(0xffffffffu, sum0, 1);
            sum0 += __shfl_xor_sync(0xffffffffu, sum0, 2);
            sum1 += __shfl_xor_sync(0xffffffffu, sum1, 1);
            sum1 += __shfl_xor_sync(0xffffffffu, sum1, 2);
            l0 = l0 * fr0 + sum0;
            l1 = l1 * fr1 + sum1;
#pragma unroll
            for (int nt = 0; nt < 8; nt++) {
                o[nt][0] *= fr0; o[nt][1] *= fr0;
                o[nt][2] *= fr1; o[nt][3] *= fr1;
            }
        }

        // pack P fragments (single fp16)
        uint32_t aP[4][4];
#pragma unroll
        for (int ks2 = 0; ks2 < 4; ks2++) {
            aP[ks2][0] = pack2h(s[2 * ks2][0],     s[2 * ks2][1]);
            aP[ks2][1] = pack2h(s[2 * ks2][2],     s[2 * ks2][3]);
            aP[ks2][2] = pack2h(s[2 * ks2 + 1][0], s[2 * ks2 + 1][1]);
            aP[ks2][3] = pack2h(s[2 * ks2 + 1][2], s[2 * ks2 + 1][3]);
        }

        // O += P @ V (V hi+lo, 2 MMAs), V fragments via ldmatrix.x4
#pragma unroll
        for (int nt = 0; nt < 8; nt++) {
            const uint32_t ro = (uint32_t)(nt * 1152);
#pragma unroll
            for (int j = 0; j < 2; j++) {
                uint32_t vh4[4], vl4[4];
                ldm4(vh_b + ro + j * 64, vh4);
                ldm4(vl_b + ro + j * 64, vl4);
                mma_f16(o[nt], aP[2 * j],     &vl4[0]);
                mma_f16(o[nt], aP[2 * j],     &vh4[0]);
                mma_f16(o[nt], aP[2 * j + 1], &vl4[2]);
                mma_f16(o[nt], aP[2 * j + 1], &vh4[2]);
            }
        }
        __syncthreads();
    }

    // normalize and write ctx
    {
        const float i0 = 1.0f / l0;
        const float i1 = 1.0f / l1;
        const long r0g = (long)(b * SS + q0 + wm + g) * DD + h * DH;
        const long r1g = (long)(b * SS + q0 + wm + g + 8) * DD + h * DH;
#pragma unroll
        for (int nt = 0; nt < 8; nt++) {
            const int dcol = nt * 8 + 2 * tg;
            float2 w0, w1;
            w0.x = o[nt][0] * i0; w0.y = o[nt][1] * i0;
            w1.x = o[nt][2] * i1; w1.y = o[nt][3] * i1;
            *reinterpret_cast<float2*>(&g_ctx[r0g + dcol]) = w0;
            *reinterpret_cast<float2*>(&g_ctx[r1g + dcol]) = w1;
        }
    }
}

// ---------------------------------------------------------------------------
// Launch
// ---------------------------------------------------------------------------
extern "C" void kernel_launch(void* const* d_in, const int* in_sizes, int n_in,
                              void* d_out, int out_size)
{
    const float* x  = (const float*)d_in[0];
    const float* Wq = (const float*)d_in[1];
    const float* bq = (const float*)d_in[2];
    const float* Wk = (const float*)d_in[3];
    const float* bk = (const float*)d_in[4];
    const float* Wv = (const float*)d_in[5];
    const float* bv = (const float*)d_in[6];
    const float* Wo = (const float*)d_in[7];
    const float* bo = (const float*)d_in[8];
    float* out = (float*)d_out;

    void *pv, *pctx, *pqh, *pql, *pkh, *pkl;
    cudaGetSymbolAddress(&pv,   g_v);
    cudaGetSymbolAddress(&pctx, g_ctx);
    cudaGetSymbolAddress(&pqh,  g_qh);
    cudaGetSymbolAddress(&pql,  g_ql);
    cudaGetSymbolAddress(&pkh,  g_kh);
    cudaGetSymbolAddress(&pkl,  g_kl);

    cudaFuncSetAttribute(attn_kernel,
                         cudaFuncAttributeMaxDynamicSharedMemorySize, ATT_SMEM);

    // fused QKV projection: z=0 -> Q (split, scaled log2e), z=1 -> K (split),
    // z=2 -> V (float)
    GemmArgs qkv;
    qkv.W[0] = Wq;  qkv.W[1] = Wk;  qkv.W[2] = Wv;
    qkv.bias[0] = bq; qkv.bias[1] = bk; qkv.bias[2] = bv;
    qkv.Cf[0] = nullptr;    qkv.Ch[0] = (uint32_t*)pqh; qkv.Cl[0] = (uint32_t*)pql;
    qkv.Cf[1] = nullptr;    qkv.Ch[1] = (uint32_t*)pkh; qkv.Cl[1] = (uint32_t*)pkl;
    qkv.Cf[2] = (float*)pv; qkv.Ch[2] = nullptr;        qkv.Cl[2] = nullptr;
    qkv.scale[0] = LOG2E; qkv.scale[1] = 1.0f; qkv.scale[2] = 1.0f;
    gemm_f16_kernel<<<dim3(DD / 128, MM / 128, 3), 256>>>(x, qkv);

    split_vt_kernel<<<dim3(32, BB * HH), 256>>>();

    dim3 agrid(SS / 128, BB * HH);    // (16, 24)
    attn_kernel<<<agrid, 256, ATT_SMEM>>>();

    GemmArgs oarg;
    oarg.W[0] = Wo; oarg.bias[0] = bo;
    oarg.Cf[0] = out; oarg.Ch[0] = nullptr; oarg.Cl[0] = nullptr;
    oarg.W[1] = Wo; oarg.bias[1] = bo; oarg.Cf[1] = nullptr; oarg.Ch[1] = nullptr; oarg.Cl[1] = nullptr;
    oarg.W[2] = Wo; oarg.bias[2] = bo; oarg.Cf[2] = nullptr; oarg.Ch[2] = nullptr; oarg.Cl[2] = nullptr;
    oarg.scale[0] = 1.0f; oarg.scale[1] = 1.0f; oarg.scale[2] = 1.0f;
    gemm_f16_kernel<<<dim3(DD / 128, MM / 128, 1), 256>>>((const float*)pctx, oarg);
}

// round 17
// speedup vs baseline: 1.0057x; 1.0057x over previous
#include <cuda_runtime.h>
#include <cuda_fp16.h>
#include <math.h>
#include <stdint.h>

#define BB 2
#define SS 2048
#define DD 768
#define HH 12
#define DH 64
#define MM (BB*SS)
#define DP (DD/2)     // 384 u32 pairs per row
#define LOG2E 1.4426950408889634f

// scratch (no allocations allowed — __device__ globals are the sanctioned path)
__device__ float g_v[MM*DD];
__device__ float g_ctx[MM*DD];
// packed fp16 hi/lo splits (Q pre-scaled by log2e)
__device__ uint32_t g_qh[MM*DP];
__device__ uint32_t g_ql[MM*DP];
__device__ uint32_t g_kh[MM*DP];
__device__ uint32_t g_kl[MM*DP];
__device__ uint32_t g_vth[MM*DP];   // V transposed: [(b*HH+h)*64 + d][kp(1024)]
__device__ uint32_t g_vtl[MM*DP];

__device__ __forceinline__ void mma_f16(float* d,
                                        const uint32_t* a,
                                        const uint32_t* b) {
    asm volatile(
        "mma.sync.aligned.m16n8k16.row.col.f32.f16.f16.f32 "
        "{%0,%1,%2,%3}, {%4,%5,%6,%7}, {%8,%9}, {%0,%1,%2,%3};"
        : "+f"(d[0]), "+f"(d[1]), "+f"(d[2]), "+f"(d[3])
        : "r"(a[0]), "r"(a[1]), "r"(a[2]), "r"(a[3]),
          "r"(b[0]), "r"(b[1]));
}

__device__ __forceinline__ void ldm4(uint32_t addr, uint32_t* r) {
    asm volatile("ldmatrix.sync.aligned.m8n8.x4.shared.b16 {%0,%1,%2,%3}, [%4];"
        : "=r"(r[0]), "=r"(r[1]), "=r"(r[2]), "=r"(r[3]) : "r"(addr));
}

__device__ __forceinline__ float ex2(float x) {
    float y;
    asm("ex2.approx.f32 %0, %1;" : "=f"(y) : "f"(x));
    return y;
}

// pack two floats into one fp16x2 (a -> low half, b -> high half)
__device__ __forceinline__ uint32_t pack2h(float a, float b) {
    uint32_t r;
    asm("cvt.rn.f16x2.f32 %0, %1, %2;" : "=r"(r) : "f"(b), "f"(a));
    return r;
}

// split (a,b) into packed fp16 hi-pair and lo-pair (low half = first element)
__device__ __forceinline__ void split2h(float a, float b,
                                        uint32_t& hi, uint32_t& lo) {
    __half ah = __float2half_rn(a);
    __half bh = __float2half_rn(b);
    hi = (uint32_t)__half_as_ushort(ah) |
         ((uint32_t)__half_as_ushort(bh) << 16);
    lo = pack2h(a - __half2float(ah), b - __half2float(bh));
}

__device__ __forceinline__ void cp16(uint32_t saddr, const void* gaddr) {
    asm volatile("cp.async.ca.shared.global [%0], [%1], 16;"
                 :: "r"(saddr), "l"(gaddr));
}
#define CP_COMMIT() asm volatile("cp.async.commit_group;" ::: "memory")
#define CP_WAIT1()  asm volatile("cp.async.wait_group 1;" ::: "memory")
#define CP_WAIT0()  asm volatile("cp.async.wait_group 0;" ::: "memory")

// ---------------------------------------------------------------------------
// fp16x2 (3-term) mma.sync GEMM with selectable epilogue. (unchanged)
// ---------------------------------------------------------------------------
struct GemmArgs {
    const float* W[3];
    const float* bias[3];
    float*    Cf[3];
    uint32_t* Ch[3];
    uint32_t* Cl[3];
    float     scale[3];
};

#define AST 9      // A smem u32 stride
#define BST 136    // B smem u32 stride

__global__ void __launch_bounds__(256)
gemm_f16_kernel(const float* __restrict__ A, GemmArgs args)
{
    __shared__ uint32_t AsH[128 * AST];
    __shared__ uint32_t AsL[128 * AST];
    __shared__ uint32_t BsH[8 * BST];
    __shared__ uint32_t BsL[8 * BST];
    __shared__ float sbias[128];

    const int z = blockIdx.z;
    const float* __restrict__ W    = args.W[z];
    const float* __restrict__ bias = args.bias[z];
    float*    Cf = args.Cf[z];
    uint32_t* Ch = args.Ch[z];
    uint32_t* Cl = args.Cl[z];
    const float scl = args.scale[z];

    const int tid  = threadIdx.x;
    const int warp = tid >> 5;
    const int lane = tid & 31;
    const int g    = lane >> 2;
    const int tg   = lane & 3;
    const int wm   = warp >> 2;
    const int wn   = warp & 3;
    const int m0   = blockIdx.y * 128;
    const int n0   = blockIdx.x * 128;

    if (tid < 128) sbias[tid] = bias[n0 + tid];

    const int ar0 = tid >> 2;
    const int aq0 = tid & 3;
    const int ar1 = (tid + 256) >> 2;
    const int aq1 = (tid + 256) & 3;
    const int bkp = tid >> 5;
    const int bnq = (tid & 31) << 2;

    float acc[4][4][4];
#pragma unroll
    for (int i = 0; i < 4; i++)
#pragma unroll
        for (int j = 0; j < 4; j++)
#pragma unroll
            for (int q = 0; q < 4; q++) acc[i][j][q] = 0.0f;

    float4 ra0, ra1, rb0, rb1;

    ra0 = *reinterpret_cast<const float4*>(&A[(long)(m0 + ar0) * DD + aq0 * 4]);
    ra1 = *reinterpret_cast<const float4*>(&A[(long)(m0 + ar1) * DD + aq1 * 4]);
    rb0 = *reinterpret_cast<const float4*>(&W[(long)(2 * bkp) * DD + n0 + bnq]);
    rb1 = *reinterpret_cast<const float4*>(&W[(long)(2 * bkp + 1) * DD + n0 + bnq]);

#define STORE_TILES() do {                                                   \
    split2h(ra0.x, ra0.y, AsH[ar0 * AST + aq0 * 2],     AsL[ar0 * AST + aq0 * 2]); \
    split2h(ra0.z, ra0.w, AsH[ar0 * AST + aq0 * 2 + 1], AsL[ar0 * AST + aq0 * 2 + 1]); \
    split2h(ra1.x, ra1.y, AsH[ar1 * AST + aq1 * 2],     AsL[ar1 * AST + aq1 * 2]); \
    split2h(ra1.z, ra1.w, AsH[ar1 * AST + aq1 * 2 + 1], AsL[ar1 * AST + aq1 * 2 + 1]); \
    split2h(rb0.x, rb1.x, BsH[bkp * BST + bnq],     BsL[bkp * BST + bnq]);     \
    split2h(rb0.y, rb1.y, BsH[bkp * BST + bnq + 1], BsL[bkp * BST + bnq + 1]); \
    split2h(rb0.z, rb1.z, BsH[bkp * BST + bnq + 2], BsL[bkp * BST + bnq + 2]); \
    split2h(rb0.w, rb1.w, BsH[bkp * BST + bnq + 3], BsL[bkp * BST + bnq + 3]); \
} while (0)

    STORE_TILES();
    __syncthreads();

    const int NITER = DD / 16;   // 48
    for (int it = 0; it < NITER; it++) {
        if (it + 1 < NITER) {
            const int k0 = (it + 1) * 16;
            ra0 = *reinterpret_cast<const float4*>(&A[(long)(m0 + ar0) * DD + k0 + aq0 * 4]);
            ra1 = *reinterpret_cast<const float4*>(&A[(long)(m0 + ar1) * DD + k0 + aq1 * 4]);
            rb0 = *reinterpret_cast<const float4*>(&W[(long)(k0 + 2 * bkp) * DD + n0 + bnq]);
            rb1 = *reinterpret_cast<const float4*>(&W[(long)(k0 + 2 * bkp + 1) * DD + n0 + bnq]);
        }

        uint32_t afH[4][4], afL[4][4], bfH[4][2], bfL[4][2];
#pragma unroll
        for (int mi = 0; mi < 4; mi++) {
            const int r = wm * 64 + mi * 16 + g;
            afH[mi][0] = AsH[r * AST + tg];
            afH[mi][1] = AsH[(r + 8) * AST + tg];
            afH[mi][2] = AsH[r * AST + tg + 4];
            afH[mi][3] = AsH[(r + 8) * AST + tg + 4];
            afL[mi][0] = AsL[r * AST + tg];
            afL[mi][1] = AsL[(r + 8) * AST + tg];
            afL[mi][2] = AsL[r * AST + tg + 4];
            afL[mi][3] = AsL[(r + 8) * AST + tg + 4];
        }
#pragma unroll
        for (int ni = 0; ni < 4; ni++) {
            const int c = wn * 32 + ni * 8 + g;
            bfH[ni][0] = BsH[tg * BST + c];
            bfH[ni][1] = BsH[(tg + 4) * BST + c];
            bfL[ni][0] = BsL[tg * BST + c];
            bfL[ni][1] = BsL[(tg + 4) * BST + c];
        }
#pragma unroll
        for (int mi = 0; mi < 4; mi++)
#pragma unroll
            for (int ni = 0; ni < 4; ni++) {
                mma_f16(acc[mi][ni], afH[mi], bfL[ni]);
                mma_f16(acc[mi][ni], afL[mi], bfH[ni]);
                mma_f16(acc[mi][ni], afH[mi], bfH[ni]);
            }
        __syncthreads();
        if (it + 1 < NITER) {
            STORE_TILES();
            __syncthreads();
        }
    }

    // epilogue
    const int rr = lane >> 2;
    const int cc = (lane & 3) * 2;
    if (Ch) {
#pragma unroll
        for (int mi = 0; mi < 4; mi++) {
#pragma unroll
            for (int ni = 0; ni < 4; ni++) {
                const int col = wn * 32 + ni * 8 + cc;
                const int row = m0 + wm * 64 + mi * 16 + rr;
                const int pc  = (n0 + col) >> 1;
                const float v0 = (acc[mi][ni][0] + sbias[col]) * scl;
                const float v1 = (acc[mi][ni][1] + sbias[col + 1]) * scl;
                const float v2 = (acc[mi][ni][2] + sbias[col]) * scl;
                const float v3 = (acc[mi][ni][3] + sbias[col + 1]) * scl;
                uint32_t hi, lo;
                split2h(v0, v1, hi, lo);
                Ch[(long)row * DP + pc] = hi;
                Cl[(long)row * DP + pc] = lo;
                split2h(v2, v3, hi, lo);
                Ch[(long)(row + 8) * DP + pc] = hi;
                Cl[(long)(row + 8) * DP + pc] = lo;
            }
        }
    } else {
#pragma unroll
        for (int mi = 0; mi < 4; mi++) {
#pragma unroll
            for (int ni = 0; ni < 4; ni++) {
                const int col = wn * 32 + ni * 8 + cc;
                const int row = m0 + wm * 64 + mi * 16 + rr;
                float2 o0, o1;
                o0.x = acc[mi][ni][0] + sbias[col];
                o0.y = acc[mi][ni][1] + sbias[col + 1];
                o1.x = acc[mi][ni][2] + sbias[col];
                o1.y = acc[mi][ni][3] + sbias[col + 1];
                *reinterpret_cast<float2*>(&Cf[(long)row * DD + n0 + col]) = o0;
                *reinterpret_cast<float2*>(&Cf[(long)(row + 8) * DD + n0 + col]) = o1;
            }
        }
    }
}

// ---------------------------------------------------------------------------
// Pre-pass: V transpose + fp16 split, tiled through smem. (unchanged)
// ---------------------------------------------------------------------------
__global__ void __launch_bounds__(256)
split_vt_kernel()
{
    __shared__ uint32_t sH[32 * 65];
    __shared__ uint32_t sL[32 * 65];

    const int tid = threadIdx.x;
    const int kp0 = blockIdx.x * 32;
    const int bh  = blockIdx.y;
    const int b   = bh / HH;
    const int h   = bh % HH;

#pragma unroll
    for (int p = 0; p < 8; p++) {
        const int idx = tid + p * 256;
        const int kp = idx >> 6, d = idx & 63;
        const long base = (long)(b * SS + 2 * (kp0 + kp)) * DD + h * DH + d;
        uint32_t hi, lo;
        split2h(g_v[base], g_v[base + DD], hi, lo);
        sH[kp * 65 + d] = hi;
        sL[kp * 65 + d] = lo;
    }
    __syncthreads();

#pragma unroll
    for (int p = 0; p < 8; p++) {
        const int idx = tid + p * 256;
        const int d = idx >> 5, kp = idx & 31;
        const long o = ((long)bh * 64 + d) * 1024 + kp0 + kp;
        g_vth[o] = sH[kp * 65 + d];
        g_vtl[o] = sL[kp * 65 + d];
    }
}

// ---------------------------------------------------------------------------
// Flash attention: fp16 mma.sync + ldmatrix, base-2 softmax, cp.async
// double-buffer. CTA = 64 queries x one (b,h); 4 warps (m16 each), 128 thr,
// 3 CTAs/SM target (221KB smem, independent CTAs hide softmax latency).
// K tiles: [key(64)][kp(32)] stride 36; V tiles: [d(64)][kp(32)] stride 36.
// ---------------------------------------------------------------------------
#define KTILE 2304                      // 64*36 u32 per array per stage
#define ATT_SMEM (8 * KTILE * 4)        // 73728 B
#define NT (SS/64)                      // 32

__global__ void __launch_bounds__(128, 3)
attn_kernel()
{
    extern __shared__ uint32_t smatt[];
    uint32_t* sKh = smatt;
    uint32_t* sKl = smatt + 2 * KTILE;
    uint32_t* sVh = smatt + 4 * KTILE;
    uint32_t* sVl = smatt + 6 * KTILE;

    const uint32_t aKh = (uint32_t)__cvta_generic_to_shared(sKh);
    const uint32_t aKl = (uint32_t)__cvta_generic_to_shared(sKl);
    const uint32_t aVh = (uint32_t)__cvta_generic_to_shared(sVh);
    const uint32_t aVl = (uint32_t)__cvta_generic_to_shared(sVl);

    const int tid  = threadIdx.x;
    const int warp = tid >> 5;
    const int lane = tid & 31;
    const int g    = lane >> 2;
    const int tg   = lane & 3;
    const int wm   = warp * 16;          // 4 warps cover 64 queries
    const int bh   = blockIdx.y;
    const int b    = bh / HH;
    const int h    = bh % HH;
    const int q0   = blockIdx.x * 64;

    const uint32_t* khg = &g_kh[(long)(b * SS) * DP + h * 32];
    const uint32_t* klg = &g_kl[(long)(b * SS) * DP + h * 32];
    const uint32_t* vhg = &g_vth[(long)bh * 64 * 1024];
    const uint32_t* vlg = &g_vtl[(long)bh * 64 * 1024];

    // staging coords: 128 threads, 16 chunks each (4 row-groups x 4 arrays)
    const int sr = tid >> 3;             // 0..15
    const int sc = (tid & 7) * 4;        // 0..28

#define ISSUE_STAGE(kt, st) do {                                             \
    const int _k0 = (kt) * 64;                                               \
    const uint32_t _so = (uint32_t)(st) * KTILE * 4;                         \
    _Pragma("unroll")                                                        \
    for (int _i = 0; _i < 4; _i++) {                                         \
        const int _r = sr + _i * 16;                                         \
        cp16(aKh + _so + (_r * 36 + sc) * 4, khg + (long)(_k0 + _r) * DP + sc); \
        cp16(aKl + _so + (_r * 36 + sc) * 4, klg + (long)(_k0 + _r) * DP + sc); \
        cp16(aVh + _so + (_r * 36 + sc) * 4, vhg + (long)_r * 1024 + (kt) * 32 + sc); \
        cp16(aVl + _so + (_r * 36 + sc) * 4, vlg + (long)_r * 1024 + (kt) * 32 + sc); \
    }                                                                        \
    CP_COMMIT();                                                             \
} while (0)

    // Q fragments to registers (once); g_qh pre-scaled by log2e
    uint32_t qH[4][4], qL[4][4];
    {
        const uint32_t* qh = &g_qh[(long)(b * SS + q0 + wm) * DP + h * 32];
        const uint32_t* ql = &g_ql[(long)(b * SS + q0 + wm) * DP + h * 32];
#pragma unroll
        for (int ks = 0; ks < 4; ks++) {
            const int c = ks * 8 + tg;
            qH[ks][0] = qh[g * DP + c];
            qH[ks][1] = qh[(g + 8) * DP + c];
            qH[ks][2] = qh[g * DP + c + 4];
            qH[ks][3] = qh[(g + 8) * DP + c + 4];
            qL[ks][0] = ql[g * DP + c];
            qL[ks][1] = ql[(g + 8) * DP + c];
            qL[ks][2] = ql[g * DP + c + 4];
            qL[ks][3] = ql[(g + 8) * DP + c + 4];
        }
    }

    // per-lane ldmatrix row offset (bytes): row = lane&7, matrix = lane>>3
    const uint32_t lmoff = (uint32_t)(((lane & 7) * 36 + (lane >> 3) * 4) * 4);

    float m0 = -INFINITY, m1 = -INFINITY, l0 = 0.0f, l1 = 0.0f;
    float o[8][4];
#pragma unroll
    for (int nt = 0; nt < 8; nt++)
#pragma unroll
        for (int q = 0; q < 4; q++) o[nt][q] = 0.0f;

    ISSUE_STAGE(0, 0);

    for (int kt = 0; kt < NT; kt++) {
        const int st = kt & 1;
        if (kt + 1 < NT) {
            ISSUE_STAGE(kt + 1, st ^ 1);
            CP_WAIT1();
        } else {
            CP_WAIT0();
        }
        __syncthreads();

        const uint32_t so = (uint32_t)st * KTILE * 4;
        const uint32_t kh_b = aKh + so + lmoff;
        const uint32_t kl_b = aKl + so + lmoff;
        const uint32_t vh_b = aVh + so + lmoff;
        const uint32_t vl_b = aVl + so + lmoff;

        // S = Q @ K^T (fp16x2, 3 terms), K fragments via ldmatrix.x4
        float s[8][4];
#pragma unroll
        for (int nt = 0; nt < 8; nt++)
#pragma unroll
            for (int q = 0; q < 4; q++) s[nt][q] = 0.0f;
#pragma unroll
        for (int nt = 0; nt < 8; nt++) {
            const uint32_t ro = (uint32_t)(nt * 1152);   // nt*8*36*4
#pragma unroll
            for (int j = 0; j < 2; j++) {
                uint32_t bh4[4], bl4[4];
                ldm4(kh_b + ro + j * 64, bh4);
                ldm4(kl_b + ro + j * 64, bl4);
                mma_f16(s[nt], qH[2 * j],     &bl4[0]);
                mma_f16(s[nt], qL[2 * j],     &bh4[0]);
                mma_f16(s[nt], qH[2 * j],     &bh4[0]);
                mma_f16(s[nt], qH[2 * j + 1], &bl4[2]);
                mma_f16(s[nt], qL[2 * j + 1], &bh4[2]);
                mma_f16(s[nt], qH[2 * j + 1], &bh4[2]);
            }
        }

        // base-2 register softmax: rows g (s[][0..1]) and g+8 (s[][2..3])
        {
            float mx0 = -INFINITY, mx1 = -INFINITY;
#pragma unroll
            for (int nt = 0; nt < 8; nt++) {
                mx0 = fmaxf(mx0, fmaxf(s[nt][0], s[nt][1]));
                mx1 = fmaxf(mx1, fmaxf(s[nt][2], s[nt][3]));
            }
            mx0 = fmaxf(mx0, __shfl_xor_sync(0xffffffffu, mx0, 1));
            mx0 = fmaxf(mx0, __shfl_xor_sync(0xffffffffu, mx0, 2));
            mx1 = fmaxf(mx1, __shfl_xor_sync(0xffffffffu, mx1, 1));
            mx1 = fmaxf(mx1, __shfl_xor_sync(0xffffffffu, mx1, 2));
            const float m0n = fmaxf(m0, mx0);
            const float m1n = fmaxf(m1, mx1);
            const float fr0 = ex2(m0 - m0n);
            const float fr1 = ex2(m1 - m1n);
            m0 = m0n; m1 = m1n;
            float sum0 = 0.0f, sum1 = 0.0f;
#pragma unroll
            for (int nt = 0; nt < 8; nt++) {
                s[nt][0] = ex2(s[nt][0] - m0n);
                s[nt][1] = ex2(s[nt][1] - m0n);
                s[nt][2] = ex2(s[nt][2] - m1n);
                s[nt][3] = ex2(s[nt][3] - m1n);
                sum0 += s[nt][0] + s[nt][1];
                sum1 += s[nt][2] + s[nt][3];
            }
            sum0 += __shfl_xor_sync(0xffffffffu, sum0, 1);
            sum0 += __shfl_xor_sync(0xffffffffu, sum0, 2);
            sum1 += __shfl_xor_sync(0xffffffffu, sum1, 1);
            sum1 += __shfl_xor_sync(0xffffffffu, sum1, 2);
            l0 = l0 * fr0 + sum0;
            l1 = l1 * fr1 + sum1;
#pragma unroll
            for (int nt = 0; nt < 8; nt++) {
                o[nt][0] *= fr0; o[nt][1] *= fr0;
                o[nt][2] *= fr1; o[nt][3] *= fr1;
            }
        }

        // pack P fragments (single fp16)
        uint32_t aP[4][4];
#pragma unroll
        for (int ks2 = 0; ks2 < 4; ks2++) {
            aP[ks2][0] = pack2h(s[2 * ks2][0],     s[2 * ks2][1]);
            aP[ks2][1] = pack2h(s[2 * ks2][2],     s[2 * ks2][3]);
            aP[ks2][2] = pack2h(s[2 * ks2 + 1][0], s[2 * ks2 + 1][1]);
            aP[ks2][3] = pack2h(s[2 * ks2 + 1][2], s[2 * ks2 + 1][3]);
        }

        // O += P @ V (V hi+lo, 2 MMAs), V fragments via ldmatrix.x4
#pragma unroll
        for (int nt = 0; nt < 8; nt++) {
            const uint32_t ro = (uint32_t)(nt * 1152);
#pragma unroll
            for (int j = 0; j < 2; j++) {
                uint32_t vh4[4], vl4[4];
                ldm4(vh_b + ro + j * 64, vh4);
                ldm4(vl_b + ro + j * 64, vl4);
                mma_f16(o[nt], aP[2 * j],     &vl4[0]);
                mma_f16(o[nt], aP[2 * j],     &vh4[0]);
                mma_f16(o[nt], aP[2 * j + 1], &vl4[2]);
                mma_f16(o[nt], aP[2 * j + 1], &vh4[2]);
            }
        }
        __syncthreads();
    }

    // normalize and write ctx
    {
        const float i0 = 1.0f / l0;
        const float i1 = 1.0f / l1;
        const long r0g = (long)(b * SS + q0 + wm + g) * DD + h * DH;
        const long r1g = (long)(b * SS + q0 + wm + g + 8) * DD + h * DH;
#pragma unroll
        for (int nt = 0; nt < 8; nt++) {
            const int dcol = nt * 8 + 2 * tg;
            float2 w0, w1;
            w0.x = o[nt][0] * i0; w0.y = o[nt][1] * i0;
            w1.x = o[nt][2] * i1; w1.y = o[nt][3] * i1;
            *reinterpret_cast<float2*>(&g_ctx[r0g + dcol]) = w0;
            *reinterpret_cast<float2*>(&g_ctx[r1g + dcol]) = w1;
        }
    }
}

// ---------------------------------------------------------------------------
// Launch
// ---------------------------------------------------------------------------
extern "C" void kernel_launch(void* const* d_in, const int* in_sizes, int n_in,
                              void* d_out, int out_size)
{
    const float* x  = (const float*)d_in[0];
    const float* Wq = (const float*)d_in[1];
    const float* bq = (const float*)d_in[2];
    const float* Wk = (const float*)d_in[3];
    const float* bk = (const float*)d_in[4];
    const float* Wv = (const float*)d_in[5];
    const float* bv = (const float*)d_in[6];
    const float* Wo = (const float*)d_in[7];
    const float* bo = (const float*)d_in[8];
    float* out = (float*)d_out;

    void *pv, *pctx, *pqh, *pql, *pkh, *pkl;
    cudaGetSymbolAddress(&pv,   g_v);
    cudaGetSymbolAddress(&pctx, g_ctx);
    cudaGetSymbolAddress(&pqh,  g_qh);
    cudaGetSymbolAddress(&pql,  g_ql);
    cudaGetSymbolAddress(&pkh,  g_kh);
    cudaGetSymbolAddress(&pkl,  g_kl);

    cudaFuncSetAttribute(attn_kernel,
                         cudaFuncAttributeMaxDynamicSharedMemorySize, ATT_SMEM);

    // fused QKV projection: z=0 -> Q (split, scaled log2e), z=1 -> K (split),
    // z=2 -> V (float)
    GemmArgs qkv;
    qkv.W[0] = Wq;  qkv.W[1] = Wk;  qkv.W[2] = Wv;
    qkv.bias[0] = bq; qkv.bias[1] = bk; qkv.bias[2] = bv;
    qkv.Cf[0] = nullptr;    qkv.Ch[0] = (uint32_t*)pqh; qkv.Cl[0] = (uint32_t*)pql;
    qkv.Cf[1] = nullptr;    qkv.Ch[1] = (uint32_t*)pkh; qkv.Cl[1] = (uint32_t*)pkl;
    qkv.Cf[2] = (float*)pv; qkv.Ch[2] = nullptr;        qkv.Cl[2] = nullptr;
    qkv.scale[0] = LOG2E; qkv.scale[1] = 1.0f; qkv.scale[2] = 1.0f;
    gemm_f16_kernel<<<dim3(DD / 128, MM / 128, 3), 256>>>(x, qkv);

    split_vt_kernel<<<dim3(32, BB * HH), 256>>>();

    dim3 agrid(SS / 64, BB * HH);     // (32, 24) = 768 CTAs, 3/SM target
    attn_kernel<<<agrid, 128, ATT_SMEM>>>();

    GemmArgs oarg;
    oarg.W[0] = Wo; oarg.bias[0] = bo;
    oarg.Cf[0] = out; oarg.Ch[0] = nullptr; oarg.Cl[0] = nullptr;
    oarg.W[1] = Wo; oarg.bias[1] = bo; oarg.Cf[1] = nullptr; oarg.Ch[1] = nullptr; oarg.Cl[1] = nullptr;
    oarg.W[2] = Wo; oarg.bias[2] = bo; oarg.Cf[2] = nullptr; oarg.Ch[2] = nullptr; oarg.Cl[2] = nullptr;
    oarg.scale[0] = 1.0f; oarg.scale[1] = 1.0f; oarg.scale[2] = 1.0f;
    gemm_f16_kernel<<<dim3(DD / 128, MM / 128, 1), 256>>>((const float*)pctx, oarg);
}